// round 13
// baseline (speedup 1.0000x reference)
#include <cuda_runtime.h>
#include <cuda_fp16.h>
#include <cstdint>

#define D 256
#define MAXN 50000
#define MP 50048            // M padded to multiple of 128
#define NB 512              // fused B rows (W1|W2 interleaved by n-tile)
#define MAXE 800000
#define SCAN_B 256

// ---------------- scratch (__device__ globals; allocation-free rule) --------
__device__ float  g_dinv[MAXN];
__device__ int    g_hist[MAXN];
__device__ int    g_off[MAXN + 1];
__device__ int    g_cursor[MAXN];
__device__ int    g_csr[MAXE];
__device__ int    g_bsum[256];
__device__ int    g_is64;
__device__ __half g_xs[MAXN * D];  // xs = dinv*x, fp16 gather source
__device__ __half g_B[NB * D];     // fused W (fp16) [n][k]

// ---------------- init: zero hist + dtype detect + B prep (fused) -----------
__global__ void k_init(const int* __restrict__ w, const float* __restrict__ W1,
                       const float* __restrict__ W2, int n, int nhb) {
    int b = blockIdx.x;
    if (b < nhb) {
        int i = b * blockDim.x + threadIdx.x;
        if (i < n) g_hist[i] = 0;
        if (b == 0) {
            __shared__ int s[256];
            int acc = 0;
            for (int k = threadIdx.x * 2 + 1; k < 4096; k += 512) acc |= w[k];
            s[threadIdx.x] = acc;
            __syncthreads();
            for (int o = 128; o > 0; o >>= 1) {
                if (threadIdx.x < o) s[threadIdx.x] |= s[threadIdx.x + o];
                __syncthreads();
            }
            if (threadIdx.x == 0) g_is64 = (s[0] == 0) ? 1 : 0;
        }
    } else {
        int nrow = b - nhb;          // 0..511
        int k = threadIdx.x;         // 0..255
        int j = nrow >> 7, l = nrow & 127;
        const float* W = (l < 64) ? W1 : W2;
        int col = j * 64 + (l & 63);
        g_B[nrow * D + k] = __float2half_rn(W[k * D + col]);
    }
}

__device__ __forceinline__ long long load_idx(const void* ei, long long pos, int is64) {
    if (is64) return ((const long long*)ei)[pos];
    return (long long)((const int*)ei)[pos];
}

// ---------------- CSR build --------------------------------------------------
__global__ void k_hist(const void* __restrict__ ei, int E, int n) {
    int e = blockIdx.x * blockDim.x + threadIdx.x;
    if (e >= E) return;
    long long dst = load_idx(ei, (long long)E + e, g_is64);
    if ((unsigned long long)dst < (unsigned long long)n)
        atomicAdd(&g_hist[dst], 1);
}
__global__ void k_scan_block(int n) {
    __shared__ int s[SCAN_B];
    int i = blockIdx.x * SCAN_B + threadIdx.x;
    int v = (i < n) ? g_hist[i] : 0;
    s[threadIdx.x] = v;
    __syncthreads();
#pragma unroll
    for (int o = 1; o < SCAN_B; o <<= 1) {
        int t = (threadIdx.x >= o) ? s[threadIdx.x - o] : 0;
        __syncthreads();
        s[threadIdx.x] += t;
        __syncthreads();
    }
    if (i < n) g_off[i] = s[threadIdx.x] - v;
    if (threadIdx.x == SCAN_B - 1) g_bsum[blockIdx.x] = s[threadIdx.x];
}
// fused spine + add + dinv
__global__ void k_scan_add(int n, int nb) {
    __shared__ int s[SCAN_B];
    int v = (threadIdx.x < nb) ? g_bsum[threadIdx.x] : 0;
    s[threadIdx.x] = v;
    __syncthreads();
#pragma unroll
    for (int o = 1; o < SCAN_B; o <<= 1) {
        int t = (threadIdx.x >= o) ? s[threadIdx.x - o] : 0;
        __syncthreads();
        s[threadIdx.x] += t;
        __syncthreads();
    }
    int spine = (blockIdx.x == 0) ? 0 : s[blockIdx.x - 1];
    int i = blockIdx.x * SCAN_B + threadIdx.x;
    if (i < n) {
        int o = g_off[i] + spine;
        g_off[i] = o;
        g_cursor[i] = o;
        g_dinv[i] = rsqrtf((float)g_hist[i] + 1.0f);   // +1 self loop
    }
    if (blockIdx.x == 0 && threadIdx.x == 0) g_off[n] = s[nb - 1];
}
// reorder edges into CSR + (grid-stride) xs = fp16(dinv*x) conversion
__global__ void k_reorder(const void* __restrict__ ei, const float* __restrict__ x,
                          int E, int n) {
    int t = blockIdx.x * blockDim.x + threadIdx.x;
    if (t < E) {
        int is64 = g_is64;
        long long s = load_idx(ei, t, is64);
        long long d = load_idx(ei, (long long)E + t, is64);
        if ((unsigned long long)d < (unsigned long long)n) {
            int pos = atomicAdd(&g_cursor[d], 1);
            int sv = ((unsigned long long)s < (unsigned long long)n) ? (int)s : (int)d;
            g_csr[pos] = sv;
        }
    }
    const float4* x4 = reinterpret_cast<const float4*>(x);
    int total = n * 32;
    int stride = gridDim.x * blockDim.x;
    for (int u = t; u < total; u += stride) {
        int row = u >> 5;
        int lane = u & 31;
        float dv = __ldg(&g_dinv[row]);
        float4 v0 = x4[(size_t)row * 64 + lane * 2];
        float4 v1 = x4[(size_t)row * 64 + lane * 2 + 1];
        union { __half h[8]; uint4 u4; } p;
        p.h[0] = __float2half_rn(v0.x * dv); p.h[1] = __float2half_rn(v0.y * dv);
        p.h[2] = __float2half_rn(v0.z * dv); p.h[3] = __float2half_rn(v0.w * dv);
        p.h[4] = __float2half_rn(v1.x * dv); p.h[5] = __float2half_rn(v1.y * dv);
        p.h[6] = __float2half_rn(v1.z * dv); p.h[7] = __float2half_rn(v1.w * dv);
        reinterpret_cast<uint4*>(g_xs)[u] = p.u4;
    }
}

// ---------------- mma / async helpers ---------------------------------------
__device__ __forceinline__ void mma16816(float c[4], const uint32_t a[4],
                                         const uint32_t b[2]) {
    asm volatile(
        "mma.sync.aligned.m16n8k16.row.col.f32.f16.f16.f32 "
        "{%0,%1,%2,%3}, {%4,%5,%6,%7}, {%8,%9}, {%0,%1,%2,%3};"
        : "+f"(c[0]), "+f"(c[1]), "+f"(c[2]), "+f"(c[3])
        : "r"(a[0]), "r"(a[1]), "r"(a[2]), "r"(a[3]), "r"(b[0]), "r"(b[1]));
}
__device__ __forceinline__ void cp16(uint32_t saddr, const void* g) {
    asm volatile("cp.async.cg.shared.global [%0], [%1], 16;"
                 :: "r"(saddr), "l"(g) : "memory");
}
__device__ __forceinline__ void cp_commit() {
    asm volatile("cp.async.commit_group;" ::: "memory");
}
__device__ __forceinline__ void ldsm_x4(uint32_t& r0, uint32_t& r1,
                                        uint32_t& r2, uint32_t& r3, uint32_t a) {
    asm volatile("ldmatrix.sync.aligned.m8n8.x4.shared.b16 {%0,%1,%2,%3}, [%4];"
                 : "=r"(r0), "=r"(r1), "=r"(r2), "=r"(r3) : "r"(a));
}
__device__ __forceinline__ uint32_t smem_u32(const void* p) {
    uint32_t a;
    asm("{ .reg .u64 t; cvta.to.shared.u64 t, %1; cvt.u32.u64 %0, t; }"
        : "=r"(a) : "l"(p));
    return a;
}

// ---------------- fused gather + dual GEMM -----------------------------------
// Phase 1: warp-gather 128 rows of z (fp32 accum) -> fp16 into smem chunk layout.
// Phase 2: loop j=0..3, HMMA dual GEMM (A resident in smem, B cp.async 2-stage),
//          epilogue relu(zW1+b1)+zW2+b2 per j-tile.
#define PITCH 40
#define A_PLANE_PAD (128 * PITCH + 32)        // 5152 halfs (64B pad -> bank shift)
#define A_TOTAL (8 * A_PLANE_PAD)             // 41216 halfs
#define B_STAGE (128 * PITCH)                 // 5120 halfs
#define B_BASE  A_TOTAL
#define SM_HALFS (B_BASE + 2 * B_STAGE)       // 51456 halfs = 102912 B

__global__ __launch_bounds__(256, 1)
void k_fused(const float* __restrict__ b1, const float* __restrict__ b2,
             float* __restrict__ out, int M) {
    extern __shared__ uint16_t sm[];
    uint32_t sb = smem_u32(sm);

    int tid = threadIdx.x;
    int wid = tid >> 5;
    int lane = tid & 31;
    int rowBase = blockIdx.x * 128;

    // ================= Phase 1: gather into smem =================
    {
        const uint4* xs4 = reinterpret_cast<const uint4*>(g_xs);
        int kc = lane >> 2;                   // chunk 0..7
        uint32_t soff = (kc * A_PLANE_PAD + (lane & 3) * 8) * 2;
        for (int i = 0; i < 16; i++) {
            int rl = wid + 8 * i;             // local row 0..127
            int r = rowBase + rl;
            union { __half h[8]; uint4 u; } ph;
            if (r < M) {
                float a[8];
                {
                    union { uint4 u; __half2 h2[4]; } v;
                    v.u = xs4[(size_t)r * 32 + lane];
#pragma unroll
                    for (int q = 0; q < 4; q++) {
                        float2 f = __half22float2(v.h2[q]);
                        a[q * 2] = f.x; a[q * 2 + 1] = f.y;
                    }
                }
                int beg = g_off[r];
                int end = g_off[r + 1];
                for (int base = beg; base < end; base += 32) {
                    int cnt = min(32, end - base);
                    int idx = (lane < cnt) ? g_csr[base + lane] : 0;
#pragma unroll 4
                    for (int ii = 0; ii < cnt; ii++) {
                        int s = __shfl_sync(0xffffffffu, idx, ii);
                        union { uint4 u; __half2 h2[4]; } v;
                        v.u = xs4[(size_t)s * 32 + lane];
#pragma unroll
                        for (int q = 0; q < 4; q++) {
                            float2 f = __half22float2(v.h2[q]);
                            a[q * 2]     += f.x;
                            a[q * 2 + 1] += f.y;
                        }
                    }
                }
                float dv = g_dinv[r];
#pragma unroll
                for (int e = 0; e < 8; e++)
                    ph.h[e] = __float2half_rn(a[e] * dv);
            } else {
                ph.u = make_uint4(0, 0, 0, 0);
            }
            *reinterpret_cast<uint4*>(
                reinterpret_cast<char*>(sm) + soff + (uint32_t)(rl * PITCH) * 2) = ph.u;
        }
    }
    __syncthreads();

    // ================= Phase 2: dual GEMM over 4 j-tiles =================
    int wm = wid >> 1;
    int wn = wid & 1;
    int g = lane >> 2;
    int tig = lane & 3;

    const uint4* B4 = reinterpret_cast<const uint4*>(g_B);
    int lr = tid >> 2;           // 0..63
    int lkg = tid & 3;

    auto issueB = [&](int t) {
        int jq = t >> 3, kcq = t & 7, st = t & 1;
        int kb4 = kcq * 4;
#pragma unroll
        for (int it = 0; it < 2; it++) {
            int r = lr + it * 64;
            uint32_t bo = sb + (B_BASE + st * B_STAGE + r * PITCH + lkg * 8) * 2;
            cp16(bo, &B4[(size_t)(jq * 128 + r) * 32 + kb4 + lkg]);
        }
        cp_commit();
    };

    issueB(0);

    int aRowSel = lane & 15;
    int aColSel = (lane >> 4) << 3;
    int bm = lane >> 3;
    int bRowSel = ((bm >> 1) << 3) + (lane & 7);
    int bColSel = (bm & 1) << 3;

    for (int j = 0; j < 4; j++) {
        float acc1[2][4][4] = {};
        float acc2[2][4][4] = {};

        for (int kc = 0; kc < 8; kc++) {
            int t = j * 8 + kc;
            int st = t & 1;
            if (t < 31) issueB(t + 1);
            if (t < 31) asm volatile("cp.async.wait_group 1;" ::: "memory");
            else        asm volatile("cp.async.wait_group 0;" ::: "memory");
            __syncthreads();

            uint32_t aS = sb + (kc * A_PLANE_PAD) * 2;
            uint32_t bS = sb + (B_BASE + st * B_STAGE) * 2;

#pragma unroll
            for (int ks = 0; ks < 2; ks++) {
                int kb = ks * 16;
                uint32_t ah[2][4];
#pragma unroll
                for (int mb = 0; mb < 2; mb++) {
                    int row = wm * 32 + mb * 16 + aRowSel;
                    uint32_t off = (row * PITCH + kb + aColSel) * 2;
                    ldsm_x4(ah[mb][0], ah[mb][1], ah[mb][2], ah[mb][3], aS + off);
                }
                uint32_t bf1[4][2], bf2[4][2];
#pragma unroll
                for (int q = 0; q < 2; q++) {
                    int n = wn * 32 + q * 16 + bRowSel;
                    uint32_t a1 = bS + (n * PITCH + kb + bColSel) * 2;
                    uint32_t a2 = bS + ((n + 64) * PITCH + kb + bColSel) * 2;
                    ldsm_x4(bf1[q * 2][0], bf1[q * 2][1],
                            bf1[q * 2 + 1][0], bf1[q * 2 + 1][1], a1);
                    ldsm_x4(bf2[q * 2][0], bf2[q * 2][1],
                            bf2[q * 2 + 1][0], bf2[q * 2 + 1][1], a2);
                }
#pragma unroll
                for (int mb = 0; mb < 2; mb++)
#pragma unroll
                    for (int nb = 0; nb < 4; nb++) {
                        mma16816(acc1[mb][nb], ah[mb], bf1[nb]);
                        mma16816(acc2[mb][nb], ah[mb], bf2[nb]);
                    }
            }
            __syncthreads();
        }

        // ---- epilogue j: out = relu(acc1 + b1) + acc2 + b2 ----
        int cb = j * 64;
#pragma unroll
        for (int mb = 0; mb < 2; mb++) {
#pragma unroll
            for (int nb = 0; nb < 4; nb++) {
                int c = cb + wn * 32 + nb * 8 + tig * 2;
                float bb1a = __ldg(&b1[c]), bb1b = __ldg(&b1[c + 1]);
                float bb2a = __ldg(&b2[c]), bb2b = __ldg(&b2[c + 1]);
#pragma unroll
                for (int h = 0; h < 2; h++) {
                    int r = rowBase + wm * 32 + mb * 16 + g + h * 8;
                    if (r >= M) continue;
                    float z1 = acc1[mb][nb][h * 2]     + bb1a;
                    float z2 = acc1[mb][nb][h * 2 + 1] + bb1b;
                    z1 = z1 > 0.0f ? z1 : 0.0f;
                    z2 = z2 > 0.0f ? z2 : 0.0f;
                    float2 o;
                    o.x = z1 + acc2[mb][nb][h * 2]     + bb2a;
                    o.y = z2 + acc2[mb][nb][h * 2 + 1] + bb2b;
                    *reinterpret_cast<float2*>(out + (size_t)r * D + c) = o;
                }
            }
        }
    }
}

// ---------------- launch ----------------
extern "C" void kernel_launch(void* const* d_in, const int* in_sizes, int n_in,
                              void* d_out, int out_size) {
    const float* x  = (const float*)d_in[0];
    const void*  ei = d_in[1];
    const float* W1 = (const float*)d_in[2];
    const float* b1 = (const float*)d_in[3];
    const float* W2 = (const float*)d_in[4];
    const float* b2 = (const float*)d_in[5];
    float* out      = (float*)d_out;

    int N = in_sizes[0] / D;   // 50000
    int E = in_sizes[1] / 2;   // 800000
    int nb = (N + SCAN_B - 1) / SCAN_B;   // 196

    static int smem_set = 0;
    if (!smem_set) {
        cudaFuncSetAttribute(k_fused, cudaFuncAttributeMaxDynamicSharedMemorySize,
                             SM_HALFS * 2);
        smem_set = 1;
    }

    int nhb = (N + 255) / 256;
    k_init<<<nhb + NB, 256>>>((const int*)ei, W1, W2, N, nhb);
    k_hist<<<(E + 255) / 256, 256>>>(ei, E, N);
    k_scan_block<<<nb, SCAN_B>>>(N);
    k_scan_add<<<nb, SCAN_B>>>(N, nb);
    k_reorder<<<(E + 255) / 256, 256>>>(ei, x, E, N);

    k_fused<<<MP / 128, 256, SM_HALFS * 2>>>(b1, b2, out, N);
}

// round 14
// speedup vs baseline: 1.7510x; 1.7510x over previous
#include <cuda_runtime.h>
#include <cuda_fp16.h>
#include <cstdint>

#define D 256
#define MAXN 50000
#define MP 50048            // M padded to multiple of 128
#define NB 512              // fused B rows (W1|W2 interleaved by n-tile)
#define MAXE 800000
#define SCAN_B 256

// ---------------- scratch (__device__ globals; allocation-free rule) --------
__device__ float  g_dinv[MAXN];
__device__ int    g_hist[MAXN];
__device__ int    g_off[MAXN + 1];
__device__ int    g_cursor[MAXN];
__device__ int    g_csr[MAXE];
__device__ int    g_bsum[256];
__device__ int    g_is64;
__device__ __half g_xs[MAXN * D];  // xs = dinv*x, fp16 gather source
__device__ __half g_A[MP * D];     // z (fp16), padded w/ zeros
__device__ __half g_B[NB * D];     // fused W (fp16) [n][k]

// ---------------- init: zero hist + dtype detect + B prep (fused) -----------
__global__ void k_init(const int* __restrict__ w, const float* __restrict__ W1,
                       const float* __restrict__ W2, int n, int nhb) {
    int b = blockIdx.x;
    if (b < nhb) {
        int i = b * blockDim.x + threadIdx.x;
        if (i < n) g_hist[i] = 0;
        if (b == 0) {
            __shared__ int s[256];
            int acc = 0;
            for (int k = threadIdx.x * 2 + 1; k < 4096; k += 512) acc |= w[k];
            s[threadIdx.x] = acc;
            __syncthreads();
            for (int o = 128; o > 0; o >>= 1) {
                if (threadIdx.x < o) s[threadIdx.x] |= s[threadIdx.x + o];
                __syncthreads();
            }
            if (threadIdx.x == 0) g_is64 = (s[0] == 0) ? 1 : 0;
        }
    } else {
        int nrow = b - nhb;          // 0..511
        int k = threadIdx.x;         // 0..255
        int j = nrow >> 7, l = nrow & 127;
        const float* W = (l < 64) ? W1 : W2;
        int col = j * 64 + (l & 63);
        g_B[nrow * D + k] = __float2half_rn(W[k * D + col]);
    }
}

__device__ __forceinline__ long long load_idx(const void* ei, long long pos, int is64) {
    if (is64) return ((const long long*)ei)[pos];
    return (long long)((const int*)ei)[pos];
}

// ---------------- CSR build --------------------------------------------------
__global__ void k_hist(const void* __restrict__ ei, int E, int n) {
    int e = blockIdx.x * blockDim.x + threadIdx.x;
    if (e >= E) return;
    long long dst = load_idx(ei, (long long)E + e, g_is64);
    if ((unsigned long long)dst < (unsigned long long)n)
        atomicAdd(&g_hist[dst], 1);
}
__global__ void k_scan_block(int n) {
    __shared__ int s[SCAN_B];
    int i = blockIdx.x * SCAN_B + threadIdx.x;
    int v = (i < n) ? g_hist[i] : 0;
    s[threadIdx.x] = v;
    __syncthreads();
#pragma unroll
    for (int o = 1; o < SCAN_B; o <<= 1) {
        int t = (threadIdx.x >= o) ? s[threadIdx.x - o] : 0;
        __syncthreads();
        s[threadIdx.x] += t;
        __syncthreads();
    }
    if (i < n) g_off[i] = s[threadIdx.x] - v;
    if (threadIdx.x == SCAN_B - 1) g_bsum[blockIdx.x] = s[threadIdx.x];
}
// fused spine + add + dinv
__global__ void k_scan_add(int n, int nb) {
    __shared__ int s[SCAN_B];
    int v = (threadIdx.x < nb) ? g_bsum[threadIdx.x] : 0;
    s[threadIdx.x] = v;
    __syncthreads();
#pragma unroll
    for (int o = 1; o < SCAN_B; o <<= 1) {
        int t = (threadIdx.x >= o) ? s[threadIdx.x - o] : 0;
        __syncthreads();
        s[threadIdx.x] += t;
        __syncthreads();
    }
    int spine = (blockIdx.x == 0) ? 0 : s[blockIdx.x - 1];
    int i = blockIdx.x * SCAN_B + threadIdx.x;
    if (i < n) {
        int o = g_off[i] + spine;
        g_off[i] = o;
        g_cursor[i] = o;
        g_dinv[i] = rsqrtf((float)g_hist[i] + 1.0f);   // +1 self loop
    }
    if (blockIdx.x == 0 && threadIdx.x == 0) g_off[n] = s[nb - 1];
}
// reorder edges into CSR + (grid-stride) xs = fp16(dinv*x) conversion
__global__ void k_reorder(const void* __restrict__ ei, const float* __restrict__ x,
                          int E, int n) {
    int t = blockIdx.x * blockDim.x + threadIdx.x;
    if (t < E) {
        int is64 = g_is64;
        long long s = load_idx(ei, t, is64);
        long long d = load_idx(ei, (long long)E + t, is64);
        if ((unsigned long long)d < (unsigned long long)n) {
            int pos = atomicAdd(&g_cursor[d], 1);
            int sv = ((unsigned long long)s < (unsigned long long)n) ? (int)s : (int)d;
            g_csr[pos] = sv;
        }
    }
    const float4* x4 = reinterpret_cast<const float4*>(x);
    int total = n * 32;
    int stride = gridDim.x * blockDim.x;
    for (int u = t; u < total; u += stride) {
        int row = u >> 5;
        int lane = u & 31;
        float dv = __ldg(&g_dinv[row]);
        float4 v0 = x4[(size_t)row * 64 + lane * 2];
        float4 v1 = x4[(size_t)row * 64 + lane * 2 + 1];
        union { __half h[8]; uint4 u4; } p;
        p.h[0] = __float2half_rn(v0.x * dv); p.h[1] = __float2half_rn(v0.y * dv);
        p.h[2] = __float2half_rn(v0.z * dv); p.h[3] = __float2half_rn(v0.w * dv);
        p.h[4] = __float2half_rn(v1.x * dv); p.h[5] = __float2half_rn(v1.y * dv);
        p.h[6] = __float2half_rn(v1.z * dv); p.h[7] = __float2half_rn(v1.w * dv);
        reinterpret_cast<uint4*>(g_xs)[u] = p.u4;
    }
}

// ---------------- fused gather + norm -> fp16 z ------------------------------
// One warp per node row r, lane covers 8 cols (one uint4 of fp16):
//   z = dinv[r] * (xs[r] + sum_e xs[csr[e]]),  fp32 accumulation.
__global__ __launch_bounds__(256)
void k_gather(int M) {
    int warp = (blockIdx.x * blockDim.x + threadIdx.x) >> 5;
    int lane = threadIdx.x & 31;
    if (warp >= MP) return;
    int r = warp;

    union { __half h[8]; uint4 u; } ph;

    if (r < M) {
        const uint4* xs4 = reinterpret_cast<const uint4*>(g_xs);
        float a[8];
        {
            union { uint4 u; __half2 h2[4]; } v;
            v.u = xs4[(size_t)r * 32 + lane];
#pragma unroll
            for (int q = 0; q < 4; q++) {
                float2 f = __half22float2(v.h2[q]);
                a[q * 2] = f.x; a[q * 2 + 1] = f.y;
            }
        }
        int beg = g_off[r];
        int end = g_off[r + 1];
        for (int base = beg; base < end; base += 32) {
            int cnt = min(32, end - base);
            int idx = (lane < cnt) ? g_csr[base + lane] : 0;
#pragma unroll 4
            for (int i = 0; i < cnt; i++) {
                int s = __shfl_sync(0xffffffffu, idx, i);
                union { uint4 u; __half2 h2[4]; } v;
                v.u = xs4[(size_t)s * 32 + lane];
#pragma unroll
                for (int q = 0; q < 4; q++) {
                    float2 f = __half22float2(v.h2[q]);
                    a[q * 2]     += f.x;
                    a[q * 2 + 1] += f.y;
                }
            }
        }
        float dv = g_dinv[r];
#pragma unroll
        for (int e = 0; e < 8; e++)
            ph.h[e] = __float2half_rn(a[e] * dv);
    } else {
        ph.u = make_uint4(0, 0, 0, 0);
    }
    reinterpret_cast<uint4*>(g_A)[(size_t)r * 32 + lane] = ph.u;
}

// ---------------- mma / async helpers ---------------------------------------
__device__ __forceinline__ void mma16816(float c[4], const uint32_t a[4],
                                         const uint32_t b[2]) {
    asm volatile(
        "mma.sync.aligned.m16n8k16.row.col.f32.f16.f16.f32 "
        "{%0,%1,%2,%3}, {%4,%5,%6,%7}, {%8,%9}, {%0,%1,%2,%3};"
        : "+f"(c[0]), "+f"(c[1]), "+f"(c[2]), "+f"(c[3])
        : "r"(a[0]), "r"(a[1]), "r"(a[2]), "r"(a[3]), "r"(b[0]), "r"(b[1]));
}
__device__ __forceinline__ void cp16(uint32_t saddr, const void* g) {
    asm volatile("cp.async.cg.shared.global [%0], [%1], 16;"
                 :: "r"(saddr), "l"(g) : "memory");
}
__device__ __forceinline__ void cp_commit() {
    asm volatile("cp.async.commit_group;" ::: "memory");
}
__device__ __forceinline__ void ldsm_x4(uint32_t& r0, uint32_t& r1,
                                        uint32_t& r2, uint32_t& r3, uint32_t a) {
    asm volatile("ldmatrix.sync.aligned.m8n8.x4.shared.b16 {%0,%1,%2,%3}, [%4];"
                 : "=r"(r0), "=r"(r1), "=r"(r2), "=r"(r3) : "r"(a));
}
__device__ __forceinline__ uint32_t smem_u32(const void* p) {
    uint32_t a;
    asm("{ .reg .u64 t; cvta.to.shared.u64 t, %1; cvt.u32.u64 %0, t; }"
        : "=r"(a) : "l"(p));
    return a;
}

// ---------------- HMMA fp16 dual GEMM, 512 thr, 2 j-tiles/CTA ---------------
// smem (halfs): A[stage][128*40] then B[stage][256*40]
#define PITCH 40
#define A_PLANE (128 * PITCH)                 // 5120 halfs
#define B_STAGE (256 * PITCH)                 // 10240 halfs (2 j-tiles of W1|W2)
#define B_BASE  (2 * A_PLANE)
#define SM_HALFS (B_BASE + 2 * B_STAGE)       // 30720 halfs = 61440 B

__global__ __launch_bounds__(512, 1)
void k_gemm_mma(const float* __restrict__ b1, const float* __restrict__ b2,
                float* __restrict__ out, int M) {
    extern __shared__ uint16_t sm[];
    uint32_t sb = smem_u32(sm);

    int tid = threadIdx.x;           // 0..511
    int wid = tid >> 5;              // 0..15
    int lane = tid & 31;
    int wm = wid >> 2;               // 0..3 : rows wm*32
    int wn = wid & 3;                // 0..3 : 128 cols in 32-col groups
    int jt = wn >> 1;                // which j-tile of the pair
    int cw = wn & 1;                 // 32-col half within the 64-col tile
    int g = lane >> 2;
    int tig = lane & 3;
    int rowBase = blockIdx.x * 128;
    int jp = blockIdx.y;             // j-pair 0..1 (tiles 2jp, 2jp+1)

    float acc1[2][4][4] = {};
    float acc2[2][4][4] = {};

    const uint4* A4 = reinterpret_cast<const uint4*>(g_A);
    const uint4* B4 = reinterpret_cast<const uint4*>(g_B);

    // loaders: A = 512 uint4/stage (1/thread), B = 1024 uint4/stage (2/thread)
    auto issue = [&](int kc, int st) {
        int kb4 = kc * 4;
        {
            int r = tid >> 2;
            int kg = tid & 3;
            uint32_t sa = sb + (st * A_PLANE + r * PITCH + kg * 8) * 2;
            cp16(sa, &A4[(size_t)(rowBase + r) * 32 + kb4 + kg]);
        }
#pragma unroll
        for (int it = 0; it < 2; it++) {
            int idx = tid + it * 512;
            int r = idx >> 2;        // 0..255
            int kg = idx & 3;
            uint32_t bo = sb + (B_BASE + st * B_STAGE + r * PITCH + kg * 8) * 2;
            cp16(bo, &B4[(size_t)(jp * 256 + r) * 32 + kb4 + kg]);
        }
        cp_commit();
    };

    issue(0, 0);

    int aRowSel = lane & 15;
    int aColSel = (lane >> 4) << 3;
    int bm = lane >> 3;
    int bRowSel = ((bm >> 1) << 3) + (lane & 7);
    int bColSel = (bm & 1) << 3;
    int nbase1 = jt * 128 + cw * 32;         // local B row of W1 block
    // W2 block at nbase1 + 64

    for (int kc = 0; kc < 8; kc++) {
        int st = kc & 1;
        if (kc < 7) issue(kc + 1, st ^ 1);
        if (kc < 7) asm volatile("cp.async.wait_group 1;" ::: "memory");
        else        asm volatile("cp.async.wait_group 0;" ::: "memory");
        __syncthreads();

        uint32_t aS = sb + (st * A_PLANE) * 2;
        uint32_t bS = sb + (B_BASE + st * B_STAGE) * 2;

#pragma unroll
        for (int ks = 0; ks < 2; ks++) {
            int kb = ks * 16;
            uint32_t ah[2][4];
#pragma unroll
            for (int mb = 0; mb < 2; mb++) {
                int row = wm * 32 + mb * 16 + aRowSel;
                uint32_t off = (row * PITCH + kb + aColSel) * 2;
                ldsm_x4(ah[mb][0], ah[mb][1], ah[mb][2], ah[mb][3], aS + off);
            }
            uint32_t bf1[4][2], bf2[4][2];
#pragma unroll
            for (int q = 0; q < 2; q++) {
                int n = nbase1 + q * 16 + bRowSel;
                uint32_t a1 = bS + (n * PITCH + kb + bColSel) * 2;
                uint32_t a2 = bS + ((n + 64) * PITCH + kb + bColSel) * 2;
                ldsm_x4(bf1[q * 2][0], bf1[q * 2][1],
                        bf1[q * 2 + 1][0], bf1[q * 2 + 1][1], a1);
                ldsm_x4(bf2[q * 2][0], bf2[q * 2][1],
                        bf2[q * 2 + 1][0], bf2[q * 2 + 1][1], a2);
            }
#pragma unroll
            for (int mb = 0; mb < 2; mb++)
#pragma unroll
                for (int nb = 0; nb < 4; nb++) {
                    mma16816(acc1[mb][nb], ah[mb], bf1[nb]);
                    mma16816(acc2[mb][nb], ah[mb], bf2[nb]);
                }
        }
        __syncthreads();
    }

    // ---- epilogue: out = relu(acc1 + b1) + acc2 + b2 ----
    int cb = jp * 128 + jt * 64 + cw * 32;
#pragma unroll
    for (int mb = 0; mb < 2; mb++) {
#pragma unroll
        for (int nb = 0; nb < 4; nb++) {
            int c = cb + nb * 8 + tig * 2;
            float bb1a = __ldg(&b1[c]), bb1b = __ldg(&b1[c + 1]);
            float bb2a = __ldg(&b2[c]), bb2b = __ldg(&b2[c + 1]);
#pragma unroll
            for (int h = 0; h < 2; h++) {
                int r = rowBase + wm * 32 + mb * 16 + g + h * 8;
                if (r >= M) continue;
                float z1 = acc1[mb][nb][h * 2]     + bb1a;
                float z2 = acc1[mb][nb][h * 2 + 1] + bb1b;
                z1 = z1 > 0.0f ? z1 : 0.0f;
                z2 = z2 > 0.0f ? z2 : 0.0f;
                float2 o;
                o.x = z1 + acc2[mb][nb][h * 2]     + bb2a;
                o.y = z2 + acc2[mb][nb][h * 2 + 1] + bb2b;
                *reinterpret_cast<float2*>(out + (size_t)r * D + c) = o;
            }
        }
    }
}

// ---------------- launch ----------------
extern "C" void kernel_launch(void* const* d_in, const int* in_sizes, int n_in,
                              void* d_out, int out_size) {
    const float* x  = (const float*)d_in[0];
    const void*  ei = d_in[1];
    const float* W1 = (const float*)d_in[2];
    const float* b1 = (const float*)d_in[3];
    const float* W2 = (const float*)d_in[4];
    const float* b2 = (const float*)d_in[5];
    float* out      = (float*)d_out;

    int N = in_sizes[0] / D;   // 50000
    int E = in_sizes[1] / 2;   // 800000
    int nb = (N + SCAN_B - 1) / SCAN_B;   // 196

    static int smem_set = 0;
    if (!smem_set) {
        cudaFuncSetAttribute(k_gemm_mma, cudaFuncAttributeMaxDynamicSharedMemorySize,
                             SM_HALFS * 2);
        smem_set = 1;
    }

    int nhb = (N + 255) / 256;
    k_init<<<nhb + NB, 256>>>((const int*)ei, W1, W2, N, nhb);
    k_hist<<<(E + 255) / 256, 256>>>(ei, E, N);
    k_scan_block<<<nb, SCAN_B>>>(N);
    k_scan_add<<<nb, SCAN_B>>>(N, nb);
    k_reorder<<<(E + 255) / 256, 256>>>(ei, x, E, N);

    k_gather<<<(MP * 32 + 255) / 256, 256>>>(N);

    dim3 grid(MP / 128, 2);
    k_gemm_mma<<<grid, 512, SM_HALFS * 2>>>(b1, b2, out, N);
}

// round 15
// speedup vs baseline: 1.7782x; 1.0156x over previous
#include <cuda_runtime.h>
#include <cuda_fp16.h>
#include <cstdint>

#define D 256
#define MAXN 50000
#define MP 50048            // M padded to multiple of 128
#define NB 512              // fused B rows (W1|W2 interleaved by n-tile)
#define MAXE 800000
#define SCAN_B 256

// ---------------- scratch (__device__ globals; allocation-free rule) --------
__device__ float  g_dinv[MAXN];
__device__ int    g_hist[MAXN];                 // zero at load; re-zeroed by k_reorder
__device__ int    g_off[MAXN + 1];
__device__ int    g_cursor[MAXN];
__device__ int    g_csr[MAXE];
__device__ unsigned long long g_state[256];     // lookback: (value<<2)|flag; zero at load
__device__ int    g_is64;
__device__ __half g_xs[MAXN * D];  // xs = dinv*x, fp16 gather source
__device__ __half g_A[MP * D];     // z (fp16), padded w/ zeros
__device__ __half g_B[NB * D];     // fused W (fp16) [n][k]

__device__ __forceinline__ long long load_idx(const void* ei, long long pos, int is64) {
    if (is64) return ((const long long*)ei)[pos];
    return (long long)((const int*)ei)[pos];
}

// ---------------- init: hist (self-detected dtype) + B prep ------------------
// Edge blocks b < eb: per-block dtype detect (256 words) + hist atomicAdd.
// Blocks >= eb: B prep. g_hist must be zero on entry (deferred-zero invariant).
__global__ void k_init_hist(const void* __restrict__ ei,
                            const float* __restrict__ W1,
                            const float* __restrict__ W2,
                            int E, int n, int eb) {
    int b = blockIdx.x;
    if (b < eb) {
        __shared__ int sdet[4];
        const int* w = (const int*)ei;
        int acc = 0;
        if (threadIdx.x < 128) acc = w[threadIdx.x * 2 + 1];
#pragma unroll
        for (int o = 16; o > 0; o >>= 1) acc |= __shfl_xor_sync(0xffffffffu, acc, o);
        if (threadIdx.x < 128 && (threadIdx.x & 31) == 0) sdet[threadIdx.x >> 5] = acc;
        __syncthreads();
        int is64 = ((sdet[0] | sdet[1] | sdet[2] | sdet[3]) == 0) ? 1 : 0;
        int e = b * 256 + threadIdx.x;
        if (e < E) {
            long long dst = load_idx(ei, (long long)E + e, is64);
            if ((unsigned long long)dst < (unsigned long long)n)
                atomicAdd(&g_hist[dst], 1);
        }
        if (b == 0 && threadIdx.x == 0) g_is64 = is64;
    } else {
        int nrow = b - eb;           // 0..511
        int k = threadIdx.x;         // 0..255
        int j = nrow >> 7, l = nrow & 127;
        const float* W = (l < 64) ? W1 : W2;
        int col = j * 64 + (l & 63);
        g_B[nrow * D + k] = __float2half_rn(W[k * D + col]);
    }
}

// ---------------- single-pass scan (decoupled lookback) + dinv ---------------
__global__ void k_scan(int n, int nb) {
    __shared__ int s[SCAN_B];
    __shared__ int sprefix;
    int bid = blockIdx.x;
    int i = bid * SCAN_B + threadIdx.x;
    int v = (i < n) ? g_hist[i] : 0;
    s[threadIdx.x] = v;
    __syncthreads();
#pragma unroll
    for (int o = 1; o < SCAN_B; o <<= 1) {
        int t = (threadIdx.x >= o) ? s[threadIdx.x - o] : 0;
        __syncthreads();
        s[threadIdx.x] += t;
        __syncthreads();
    }
    int incl = s[threadIdx.x];          // block-local inclusive
    int total = s[SCAN_B - 1];          // block aggregate

    if (threadIdx.x == 0) {
        if (bid == 0) {
            atomicExch(&g_state[0], ((unsigned long long)total << 2) | 2ull);
            sprefix = 0;
        } else {
            atomicExch(&g_state[bid], ((unsigned long long)total << 2) | 1ull);
            int run = 0;
            int p = bid - 1;
            while (p >= 0) {
                unsigned long long st;
                do { st = atomicAdd(&g_state[p], 0ull); } while ((st & 3ull) == 0ull);
                run += (int)(st >> 2);
                if ((st & 3ull) == 2ull) break;
                p--;
            }
            atomicExch(&g_state[bid],
                       ((unsigned long long)(run + total) << 2) | 2ull);
            sprefix = run;
        }
    }
    __syncthreads();
    int spine = sprefix;
    if (i < n) {
        int o = spine + incl - v;       // global exclusive
        g_off[i] = o;
        g_cursor[i] = o;
        g_dinv[i] = rsqrtf((float)g_hist[i] + 1.0f);   // +1 self loop
    }
    if (bid == nb - 1 && threadIdx.x == 0) g_off[n] = spine + total;
}

// ---------------- reorder + xs conversion + deferred re-zero -----------------
__global__ void k_reorder(const void* __restrict__ ei, const float* __restrict__ x,
                          int E, int n) {
    int t = blockIdx.x * blockDim.x + threadIdx.x;
    if (t < E) {
        int is64 = g_is64;
        long long s = load_idx(ei, t, is64);
        long long d = load_idx(ei, (long long)E + t, is64);
        if ((unsigned long long)d < (unsigned long long)n) {
            int pos = atomicAdd(&g_cursor[d], 1);
            int sv = ((unsigned long long)s < (unsigned long long)n) ? (int)s : (int)d;
            g_csr[pos] = sv;
        }
    }
    // deferred zero for next call (hist and lookback state already consumed)
    if (t < n) g_hist[t] = 0;
    if (t < 256) g_state[t] = 0ull;
    // xs conversion: one unit = 8 elements (uint4 of fp16)
    const float4* x4 = reinterpret_cast<const float4*>(x);
    int total = n * 32;
    int stride = gridDim.x * blockDim.x;
    for (int u = t; u < total; u += stride) {
        int row = u >> 5;
        int lane = u & 31;
        float dv = __ldg(&g_dinv[row]);
        float4 v0 = x4[(size_t)row * 64 + lane * 2];
        float4 v1 = x4[(size_t)row * 64 + lane * 2 + 1];
        union { __half h[8]; uint4 u4; } p;
        p.h[0] = __float2half_rn(v0.x * dv); p.h[1] = __float2half_rn(v0.y * dv);
        p.h[2] = __float2half_rn(v0.z * dv); p.h[3] = __float2half_rn(v0.w * dv);
        p.h[4] = __float2half_rn(v1.x * dv); p.h[5] = __float2half_rn(v1.y * dv);
        p.h[6] = __float2half_rn(v1.z * dv); p.h[7] = __float2half_rn(v1.w * dv);
        reinterpret_cast<uint4*>(g_xs)[u] = p.u4;
    }
}

// ---------------- fused gather + norm -> fp16 z ------------------------------
__global__ __launch_bounds__(256)
void k_gather(int M) {
    int warp = (blockIdx.x * blockDim.x + threadIdx.x) >> 5;
    int lane = threadIdx.x & 31;
    if (warp >= MP) return;
    int r = warp;

    union { __half h[8]; uint4 u; } ph;

    if (r < M) {
        const uint4* xs4 = reinterpret_cast<const uint4*>(g_xs);
        float a[8];
        {
            union { uint4 u; __half2 h2[4]; } v;
            v.u = xs4[(size_t)r * 32 + lane];
#pragma unroll
            for (int q = 0; q < 4; q++) {
                float2 f = __half22float2(v.h2[q]);
                a[q * 2] = f.x; a[q * 2 + 1] = f.y;
            }
        }
        int beg = g_off[r];
        int end = g_off[r + 1];
        for (int base = beg; base < end; base += 32) {
            int cnt = min(32, end - base);
            int idx = (lane < cnt) ? g_csr[base + lane] : 0;
#pragma unroll 4
            for (int i = 0; i < cnt; i++) {
                int s = __shfl_sync(0xffffffffu, idx, i);
                union { uint4 u; __half2 h2[4]; } v;
                v.u = xs4[(size_t)s * 32 + lane];
#pragma unroll
                for (int q = 0; q < 4; q++) {
                    float2 f = __half22float2(v.h2[q]);
                    a[q * 2]     += f.x;
                    a[q * 2 + 1] += f.y;
                }
            }
        }
        float dv = g_dinv[r];
#pragma unroll
        for (int e = 0; e < 8; e++)
            ph.h[e] = __float2half_rn(a[e] * dv);
    } else {
        ph.u = make_uint4(0, 0, 0, 0);
    }
    reinterpret_cast<uint4*>(g_A)[(size_t)r * 32 + lane] = ph.u;
}

// ---------------- mma / async helpers ---------------------------------------
__device__ __forceinline__ void mma16816(float c[4], const uint32_t a[4],
                                         const uint32_t b[2]) {
    asm volatile(
        "mma.sync.aligned.m16n8k16.row.col.f32.f16.f16.f32 "
        "{%0,%1,%2,%3}, {%4,%5,%6,%7}, {%8,%9}, {%0,%1,%2,%3};"
        : "+f"(c[0]), "+f"(c[1]), "+f"(c[2]), "+f"(c[3])
        : "r"(a[0]), "r"(a[1]), "r"(a[2]), "r"(a[3]), "r"(b[0]), "r"(b[1]));
}
__device__ __forceinline__ void cp16(uint32_t saddr, const void* g) {
    asm volatile("cp.async.cg.shared.global [%0], [%1], 16;"
                 :: "r"(saddr), "l"(g) : "memory");
}
__device__ __forceinline__ void cp_commit() {
    asm volatile("cp.async.commit_group;" ::: "memory");
}
__device__ __forceinline__ void ldsm_x4(uint32_t& r0, uint32_t& r1,
                                        uint32_t& r2, uint32_t& r3, uint32_t a) {
    asm volatile("ldmatrix.sync.aligned.m8n8.x4.shared.b16 {%0,%1,%2,%3}, [%4];"
                 : "=r"(r0), "=r"(r1), "=r"(r2), "=r"(r3) : "r"(a));
}
__device__ __forceinline__ uint32_t smem_u32(const void* p) {
    uint32_t a;
    asm("{ .reg .u64 t; cvta.to.shared.u64 t, %1; cvt.u32.u64 %0, t; }"
        : "=r"(a) : "l"(p));
    return a;
}

// ---------------- HMMA fp16 dual GEMM, cp.async 2-stage (R12 config) --------
#define PITCH 40
#define A_PLANE (128 * PITCH)                 // 5120 halfs
#define B_STAGE (128 * PITCH)                 // 5120 halfs (64 W1 + 64 W2 rows)
#define B_BASE  (2 * A_PLANE)
#define SM_HALFS (B_BASE + 2 * B_STAGE)       // 20480 halfs = 40 KB

__global__ __launch_bounds__(256, 2)
void k_gemm_mma(const float* __restrict__ b1, const float* __restrict__ b2,
                float* __restrict__ out, int M) {
    extern __shared__ uint16_t sm[];
    uint32_t sb = smem_u32(sm);

    int tid = threadIdx.x;
    int wid = tid >> 5;
    int lane = tid & 31;
    int wm = wid >> 1;
    int wn = wid & 1;
    int g = lane >> 2;
    int tig = lane & 3;
    int rowBase = blockIdx.x * 128;
    int j = blockIdx.y;
    int cb = j * 64;

    float acc1[2][4][4] = {};
    float acc2[2][4][4] = {};

    const uint4* A4 = reinterpret_cast<const uint4*>(g_A);
    const uint4* B4 = reinterpret_cast<const uint4*>(g_B);

    int lr = tid >> 2;           // 0..63
    int lkg = tid & 3;           // 16B chunk

    auto issue = [&](int kc, int st) {
        int kb4 = kc * 4;
#pragma unroll
        for (int it = 0; it < 2; it++) {
            int r = lr + it * 64;
            uint32_t sa = sb + (st * A_PLANE + r * PITCH + lkg * 8) * 2;
            cp16(sa, &A4[(size_t)(rowBase + r) * 32 + kb4 + lkg]);
            uint32_t bo = sb + (B_BASE + st * B_STAGE + r * PITCH + lkg * 8) * 2;
            cp16(bo, &B4[(size_t)(j * 128 + r) * 32 + kb4 + lkg]);
        }
        cp_commit();
    };

    issue(0, 0);

    int aRowSel = lane & 15;
    int aColSel = (lane >> 4) << 3;
    int bm = lane >> 3;
    int bRowSel = ((bm >> 1) << 3) + (lane & 7);
    int bColSel = (bm & 1) << 3;

    for (int kc = 0; kc < 8; kc++) {
        int st = kc & 1;
        if (kc < 7) issue(kc + 1, st ^ 1);
        if (kc < 7) asm volatile("cp.async.wait_group 1;" ::: "memory");
        else        asm volatile("cp.async.wait_group 0;" ::: "memory");
        __syncthreads();

        uint32_t aS = sb + (st * A_PLANE) * 2;
        uint32_t bS = sb + (B_BASE + st * B_STAGE) * 2;

#pragma unroll
        for (int ks = 0; ks < 2; ks++) {
            int kb = ks * 16;
            uint32_t ah[2][4];
#pragma unroll
            for (int mb = 0; mb < 2; mb++) {
                int row = wm * 32 + mb * 16 + aRowSel;
                uint32_t off = (row * PITCH + kb + aColSel) * 2;
                ldsm_x4(ah[mb][0], ah[mb][1], ah[mb][2], ah[mb][3], aS + off);
            }
            uint32_t bf1[4][2], bf2[4][2];
#pragma unroll
            for (int q = 0; q < 2; q++) {
                int n = wn * 32 + q * 16 + bRowSel;
                uint32_t a1 = bS + (n * PITCH + kb + bColSel) * 2;
                uint32_t a2 = bS + ((n + 64) * PITCH + kb + bColSel) * 2;
                ldsm_x4(bf1[q * 2][0], bf1[q * 2][1],
                        bf1[q * 2 + 1][0], bf1[q * 2 + 1][1], a1);
                ldsm_x4(bf2[q * 2][0], bf2[q * 2][1],
                        bf2[q * 2 + 1][0], bf2[q * 2 + 1][1], a2);
            }
#pragma unroll
            for (int mb = 0; mb < 2; mb++)
#pragma unroll
                for (int nb = 0; nb < 4; nb++) {
                    mma16816(acc1[mb][nb], ah[mb], bf1[nb]);
                    mma16816(acc2[mb][nb], ah[mb], bf2[nb]);
                }
        }
        __syncthreads();
    }

    // ---- epilogue: out = relu(acc1 + b1) + acc2 + b2 ----
#pragma unroll
    for (int mb = 0; mb < 2; mb++) {
#pragma unroll
        for (int nb = 0; nb < 4; nb++) {
            int c = cb + wn * 32 + nb * 8 + tig * 2;
            float bb1a = __ldg(&b1[c]), bb1b = __ldg(&b1[c + 1]);
            float bb2a = __ldg(&b2[c]), bb2b = __ldg(&b2[c + 1]);
#pragma unroll
            for (int h = 0; h < 2; h++) {
                int r = rowBase + wm * 32 + mb * 16 + g + h * 8;
                if (r >= M) continue;
                float z1 = acc1[mb][nb][h * 2]     + bb1a;
                float z2 = acc1[mb][nb][h * 2 + 1] + bb1b;
                z1 = z1 > 0.0f ? z1 : 0.0f;
                z2 = z2 > 0.0f ? z2 : 0.0f;
                float2 o;
                o.x = z1 + acc2[mb][nb][h * 2]     + bb2a;
                o.y = z2 + acc2[mb][nb][h * 2 + 1] + bb2b;
                *reinterpret_cast<float2*>(out + (size_t)r * D + c) = o;
            }
        }
    }
}

// ---------------- launch ----------------
extern "C" void kernel_launch(void* const* d_in, const int* in_sizes, int n_in,
                              void* d_out, int out_size) {
    const float* x  = (const float*)d_in[0];
    const void*  ei = d_in[1];
    const float* W1 = (const float*)d_in[2];
    const float* b1 = (const float*)d_in[3];
    const float* W2 = (const float*)d_in[4];
    const float* b2 = (const float*)d_in[5];
    float* out      = (float*)d_out;

    int N = in_sizes[0] / D;   // 50000
    int E = in_sizes[1] / 2;   // 800000
    int nb = (N + SCAN_B - 1) / SCAN_B;   // 196
    int eb = (E + 255) / 256;             // 3125

    static int smem_set = 0;
    if (!smem_set) {
        cudaFuncSetAttribute(k_gemm_mma, cudaFuncAttributeMaxDynamicSharedMemorySize,
                             SM_HALFS * 2);
        smem_set = 1;
    }

    k_init_hist<<<eb + NB, 256>>>(ei, W1, W2, E, N, eb);
    k_scan<<<nb, SCAN_B>>>(N, nb);
    k_reorder<<<eb, 256>>>(ei, x, E, N);
    k_gather<<<(MP * 32 + 255) / 256, 256>>>(N);

    dim3 grid(MP / 128, 4);
    k_gemm_mma<<<grid, 256, SM_HALFS * 2>>>(b1, b2, out, N);
}

// round 16
// speedup vs baseline: 1.8620x; 1.0471x over previous
#include <cuda_runtime.h>
#include <cuda_fp16.h>
#include <cstdint>

#define D 256
#define MAXN 50000
#define MP 50048            // M padded to multiple of 128
#define NB 512              // fused B rows (W1|W2 interleaved by n-tile)
#define MAXE 800000
#define SCAN_B 256

// ---------------- scratch (__device__ globals; allocation-free rule) --------
__device__ float  g_dinv[MAXN];
__device__ int    g_hist[MAXN];                 // zero at load; re-zeroed by k_reorder
__device__ int    g_off[MAXN + 1];
__device__ int    g_cursor[MAXN];
__device__ int    g_csr[MAXE];
__device__ unsigned long long g_state[256];     // lookback: (value<<2)|flag; zero at load
__device__ int    g_is64;
__device__ __half g_xs[MAXN * D];  // xs = dinv*x, fp16 gather source
__device__ __half g_A[MP * D];     // z (fp16), padded w/ zeros
__device__ __half g_B[NB * D];     // fused W (fp16) [n][k]

__device__ __forceinline__ long long load_idx(const void* ei, long long pos, int is64) {
    if (is64) return ((const long long*)ei)[pos];
    return (long long)((const int*)ei)[pos];
}

// ---------------- init: hist (self-detected dtype) + B prep ------------------
__global__ void k_init_hist(const void* __restrict__ ei,
                            const float* __restrict__ W1,
                            const float* __restrict__ W2,
                            int E, int n, int eb) {
    int b = blockIdx.x;
    if (b < eb) {
        __shared__ int sdet[4];
        const int* w = (const int*)ei;
        int acc = 0;
        if (threadIdx.x < 128) acc = w[threadIdx.x * 2 + 1];
#pragma unroll
        for (int o = 16; o > 0; o >>= 1) acc |= __shfl_xor_sync(0xffffffffu, acc, o);
        if (threadIdx.x < 128 && (threadIdx.x & 31) == 0) sdet[threadIdx.x >> 5] = acc;
        __syncthreads();
        int is64 = ((sdet[0] | sdet[1] | sdet[2] | sdet[3]) == 0) ? 1 : 0;
        int e = b * 256 + threadIdx.x;
        if (e < E) {
            long long dst = load_idx(ei, (long long)E + e, is64);
            if ((unsigned long long)dst < (unsigned long long)n)
                atomicAdd(&g_hist[dst], 1);
        }
        if (b == 0 && threadIdx.x == 0) g_is64 = is64;
    } else {
        int nrow = b - eb;           // 0..511
        int k = threadIdx.x;         // 0..255
        int j = nrow >> 7, l = nrow & 127;
        const float* W = (l < 64) ? W1 : W2;
        int col = j * 64 + (l & 63);
        g_B[nrow * D + k] = __float2half_rn(W[k * D + col]);
    }
}

// ---------------- single-pass scan (decoupled lookback) + dinv ---------------
__global__ void k_scan(int n, int nb) {
    __shared__ int s[SCAN_B];
    __shared__ int sprefix;
    int bid = blockIdx.x;
    int i = bid * SCAN_B + threadIdx.x;
    int v = (i < n) ? g_hist[i] : 0;
    s[threadIdx.x] = v;
    __syncthreads();
#pragma unroll
    for (int o = 1; o < SCAN_B; o <<= 1) {
        int t = (threadIdx.x >= o) ? s[threadIdx.x - o] : 0;
        __syncthreads();
        s[threadIdx.x] += t;
        __syncthreads();
    }
    int incl = s[threadIdx.x];
    int total = s[SCAN_B - 1];

    if (threadIdx.x == 0) {
        if (bid == 0) {
            atomicExch(&g_state[0], ((unsigned long long)total << 2) | 2ull);
            sprefix = 0;
        } else {
            atomicExch(&g_state[bid], ((unsigned long long)total << 2) | 1ull);
            int run = 0;
            int p = bid - 1;
            while (p >= 0) {
                unsigned long long st;
                do { st = atomicAdd(&g_state[p], 0ull); } while ((st & 3ull) == 0ull);
                run += (int)(st >> 2);
                if ((st & 3ull) == 2ull) break;
                p--;
            }
            atomicExch(&g_state[bid],
                       ((unsigned long long)(run + total) << 2) | 2ull);
            sprefix = run;
        }
    }
    __syncthreads();
    int spine = sprefix;
    if (i < n) {
        int o = spine + incl - v;
        g_off[i] = o;
        g_cursor[i] = o;
        g_dinv[i] = rsqrtf((float)g_hist[i] + 1.0f);   // +1 self loop
    }
    if (bid == nb - 1 && threadIdx.x == 0) g_off[n] = spine + total;
}

// ---------------- reorder + xs conversion + deferred re-zero -----------------
__global__ void k_reorder(const void* __restrict__ ei, const float* __restrict__ x,
                          int E, int n) {
    int t = blockIdx.x * blockDim.x + threadIdx.x;
    if (t < E) {
        int is64 = g_is64;
        long long s = load_idx(ei, t, is64);
        long long d = load_idx(ei, (long long)E + t, is64);
        if ((unsigned long long)d < (unsigned long long)n) {
            int pos = atomicAdd(&g_cursor[d], 1);
            int sv = ((unsigned long long)s < (unsigned long long)n) ? (int)s : (int)d;
            g_csr[pos] = sv;
        }
    }
    if (t < n) g_hist[t] = 0;
    if (t < 256) g_state[t] = 0ull;
    const float4* x4 = reinterpret_cast<const float4*>(x);
    int total = n * 32;
    int stride = gridDim.x * blockDim.x;
    for (int u = t; u < total; u += stride) {
        int row = u >> 5;
        int lane = u & 31;
        float dv = __ldg(&g_dinv[row]);
        float4 v0 = x4[(size_t)row * 64 + lane * 2];
        float4 v1 = x4[(size_t)row * 64 + lane * 2 + 1];
        union { __half h[8]; uint4 u4; } p;
        p.h[0] = __float2half_rn(v0.x * dv); p.h[1] = __float2half_rn(v0.y * dv);
        p.h[2] = __float2half_rn(v0.z * dv); p.h[3] = __float2half_rn(v0.w * dv);
        p.h[4] = __float2half_rn(v1.x * dv); p.h[5] = __float2half_rn(v1.y * dv);
        p.h[6] = __float2half_rn(v1.z * dv); p.h[7] = __float2half_rn(v1.w * dv);
        reinterpret_cast<uint4*>(g_xs)[u] = p.u4;
    }
}

// ---------------- fused gather + norm -> fp16 z ------------------------------
// One warp per node row r, lane covers 8 cols (one uint4 of fp16).
// Edges processed in PAIRS: fp16 __hadd2 pair-sum, then one fp32 convert+add.
//   z = dinv[r] * (xs[r] + sum_e xs[csr[e]])
__global__ __launch_bounds__(256)
void k_gather(int M) {
    int warp = (blockIdx.x * blockDim.x + threadIdx.x) >> 5;
    int lane = threadIdx.x & 31;
    if (warp >= MP) return;
    int r = warp;

    union { __half h[8]; uint4 u; } ph;

    if (r < M) {
        const uint4* xs4 = reinterpret_cast<const uint4*>(g_xs);
        float a[8];
        {
            union { uint4 u; __half2 h2[4]; } v;
            v.u = xs4[(size_t)r * 32 + lane];
#pragma unroll
            for (int q = 0; q < 4; q++) {
                float2 f = __half22float2(v.h2[q]);
                a[q * 2] = f.x; a[q * 2 + 1] = f.y;
            }
        }
        int beg = g_off[r];
        int end = g_off[r + 1];
        for (int base = beg; base < end; base += 32) {
            int cnt = min(32, end - base);
            int idx = (lane < cnt) ? g_csr[base + lane] : 0;
            int i = 0;
#pragma unroll 2
            for (; i + 2 <= cnt; i += 2) {
                int s0 = __shfl_sync(0xffffffffu, idx, i);
                int s1 = __shfl_sync(0xffffffffu, idx, i + 1);
                union { uint4 u; __half2 h2[4]; } v0, v1;
                v0.u = xs4[(size_t)s0 * 32 + lane];
                v1.u = xs4[(size_t)s1 * 32 + lane];
#pragma unroll
                for (int q = 0; q < 4; q++) {
                    __half2 hs = __hadd2(v0.h2[q], v1.h2[q]);   // fp16 pair-sum
                    float2 f = __half22float2(hs);
                    a[q * 2]     += f.x;
                    a[q * 2 + 1] += f.y;
                }
            }
            if (i < cnt) {   // odd tail
                int s0 = __shfl_sync(0xffffffffu, idx, i);
                union { uint4 u; __half2 h2[4]; } v0;
                v0.u = xs4[(size_t)s0 * 32 + lane];
#pragma unroll
                for (int q = 0; q < 4; q++) {
                    float2 f = __half22float2(v0.h2[q]);
                    a[q * 2]     += f.x;
                    a[q * 2 + 1] += f.y;
                }
            }
        }
        float dv = g_dinv[r];
#pragma unroll
        for (int e = 0; e < 8; e++)
            ph.h[e] = __float2half_rn(a[e] * dv);
    } else {
        ph.u = make_uint4(0, 0, 0, 0);
    }
    reinterpret_cast<uint4*>(g_A)[(size_t)r * 32 + lane] = ph.u;
}

// ---------------- mma / async helpers ---------------------------------------
__device__ __forceinline__ void mma16816(float c[4], const uint32_t a[4],
                                         const uint32_t b[2]) {
    asm volatile(
        "mma.sync.aligned.m16n8k16.row.col.f32.f16.f16.f32 "
        "{%0,%1,%2,%3}, {%4,%5,%6,%7}, {%8,%9}, {%0,%1,%2,%3};"
        : "+f"(c[0]), "+f"(c[1]), "+f"(c[2]), "+f"(c[3])
        : "r"(a[0]), "r"(a[1]), "r"(a[2]), "r"(a[3]), "r"(b[0]), "r"(b[1]));
}
__device__ __forceinline__ void cp16(uint32_t saddr, const void* g) {
    asm volatile("cp.async.cg.shared.global [%0], [%1], 16;"
                 :: "r"(saddr), "l"(g) : "memory");
}
__device__ __forceinline__ void cp_commit() {
    asm volatile("cp.async.commit_group;" ::: "memory");
}
__device__ __forceinline__ void ldsm_x4(uint32_t& r0, uint32_t& r1,
                                        uint32_t& r2, uint32_t& r3, uint32_t a) {
    asm volatile("ldmatrix.sync.aligned.m8n8.x4.shared.b16 {%0,%1,%2,%3}, [%4];"
                 : "=r"(r0), "=r"(r1), "=r"(r2), "=r"(r3) : "r"(a));
}
__device__ __forceinline__ uint32_t smem_u32(const void* p) {
    uint32_t a;
    asm("{ .reg .u64 t; cvta.to.shared.u64 t, %1; cvt.u32.u64 %0, t; }"
        : "=r"(a) : "l"(p));
    return a;
}

// ---------------- HMMA fp16 dual GEMM, cp.async 2-stage (R12 config) --------
#define PITCH 40
#define A_PLANE (128 * PITCH)                 // 5120 halfs
#define B_STAGE (128 * PITCH)                 // 5120 halfs (64 W1 + 64 W2 rows)
#define B_BASE  (2 * A_PLANE)
#define SM_HALFS (B_BASE + 2 * B_STAGE)       // 20480 halfs = 40 KB

__global__ __launch_bounds__(256, 2)
void k_gemm_mma(const float* __restrict__ b1, const float* __restrict__ b2,
                float* __restrict__ out, int M) {
    extern __shared__ uint16_t sm[];
    uint32_t sb = smem_u32(sm);

    int tid = threadIdx.x;
    int wid = tid >> 5;
    int lane = tid & 31;
    int wm = wid >> 1;
    int wn = wid & 1;
    int g = lane >> 2;
    int tig = lane & 3;
    int rowBase = blockIdx.x * 128;
    int j = blockIdx.y;
    int cb = j * 64;

    float acc1[2][4][4] = {};
    float acc2[2][4][4] = {};

    const uint4* A4 = reinterpret_cast<const uint4*>(g_A);
    const uint4* B4 = reinterpret_cast<const uint4*>(g_B);

    int lr = tid >> 2;           // 0..63
    int lkg = tid & 3;           // 16B chunk

    auto issue = [&](int kc, int st) {
        int kb4 = kc * 4;
#pragma unroll
        for (int it = 0; it < 2; it++) {
            int r = lr + it * 64;
            uint32_t sa = sb + (st * A_PLANE + r * PITCH + lkg * 8) * 2;
            cp16(sa, &A4[(size_t)(rowBase + r) * 32 + kb4 + lkg]);
            uint32_t bo = sb + (B_BASE + st * B_STAGE + r * PITCH + lkg * 8) * 2;
            cp16(bo, &B4[(size_t)(j * 128 + r) * 32 + kb4 + lkg]);
        }
        cp_commit();
    };

    issue(0, 0);

    int aRowSel = lane & 15;
    int aColSel = (lane >> 4) << 3;
    int bm = lane >> 3;
    int bRowSel = ((bm >> 1) << 3) + (lane & 7);
    int bColSel = (bm & 1) << 3;

    for (int kc = 0; kc < 8; kc++) {
        int st = kc & 1;
        if (kc < 7) issue(kc + 1, st ^ 1);
        if (kc < 7) asm volatile("cp.async.wait_group 1;" ::: "memory");
        else        asm volatile("cp.async.wait_group 0;" ::: "memory");
        __syncthreads();

        uint32_t aS = sb + (st * A_PLANE) * 2;
        uint32_t bS = sb + (B_BASE + st * B_STAGE) * 2;

#pragma unroll
        for (int ks = 0; ks < 2; ks++) {
            int kb = ks * 16;
            uint32_t ah[2][4];
#pragma unroll
            for (int mb = 0; mb < 2; mb++) {
                int row = wm * 32 + mb * 16 + aRowSel;
                uint32_t off = (row * PITCH + kb + aColSel) * 2;
                ldsm_x4(ah[mb][0], ah[mb][1], ah[mb][2], ah[mb][3], aS + off);
            }
            uint32_t bf1[4][2], bf2[4][2];
#pragma unroll
            for (int q = 0; q < 2; q++) {
                int n = wn * 32 + q * 16 + bRowSel;
                uint32_t a1 = bS + (n * PITCH + kb + bColSel) * 2;
                uint32_t a2 = bS + ((n + 64) * PITCH + kb + bColSel) * 2;
                ldsm_x4(bf1[q * 2][0], bf1[q * 2][1],
                        bf1[q * 2 + 1][0], bf1[q * 2 + 1][1], a1);
                ldsm_x4(bf2[q * 2][0], bf2[q * 2][1],
                        bf2[q * 2 + 1][0], bf2[q * 2 + 1][1], a2);
            }
#pragma unroll
            for (int mb = 0; mb < 2; mb++)
#pragma unroll
                for (int nb = 0; nb < 4; nb++) {
                    mma16816(acc1[mb][nb], ah[mb], bf1[nb]);
                    mma16816(acc2[mb][nb], ah[mb], bf2[nb]);
                }
        }
        __syncthreads();
    }

    // ---- epilogue: out = relu(acc1 + b1) + acc2 + b2 ----
#pragma unroll
    for (int mb = 0; mb < 2; mb++) {
#pragma unroll
        for (int nb = 0; nb < 4; nb++) {
            int c = cb + wn * 32 + nb * 8 + tig * 2;
            float bb1a = __ldg(&b1[c]), bb1b = __ldg(&b1[c + 1]);
            float bb2a = __ldg(&b2[c]), bb2b = __ldg(&b2[c + 1]);
#pragma unroll
            for (int h = 0; h < 2; h++) {
                int r = rowBase + wm * 32 + mb * 16 + g + h * 8;
                if (r >= M) continue;
                float z1 = acc1[mb][nb][h * 2]     + bb1a;
                float z2 = acc1[mb][nb][h * 2 + 1] + bb1b;
                z1 = z1 > 0.0f ? z1 : 0.0f;
                z2 = z2 > 0.0f ? z2 : 0.0f;
                float2 o;
                o.x = z1 + acc2[mb][nb][h * 2]     + bb2a;
                o.y = z2 + acc2[mb][nb][h * 2 + 1] + bb2b;
                *reinterpret_cast<float2*>(out + (size_t)r * D + c) = o;
            }
        }
    }
}

// ---------------- launch ----------------
extern "C" void kernel_launch(void* const* d_in, const int* in_sizes, int n_in,
                              void* d_out, int out_size) {
    const float* x  = (const float*)d_in[0];
    const void*  ei = d_in[1];
    const float* W1 = (const float*)d_in[2];
    const float* b1 = (const float*)d_in[3];
    const float* W2 = (const float*)d_in[4];
    const float* b2 = (const float*)d_in[5];
    float* out      = (float*)d_out;

    int N = in_sizes[0] / D;   // 50000
    int E = in_sizes[1] / 2;   // 800000
    int nb = (N + SCAN_B - 1) / SCAN_B;   // 196
    int eb = (E + 255) / 256;             // 3125

    static int smem_set = 0;
    if (!smem_set) {
        cudaFuncSetAttribute(k_gemm_mma, cudaFuncAttributeMaxDynamicSharedMemorySize,
                             SM_HALFS * 2);
        smem_set = 1;
    }

    k_init_hist<<<eb + NB, 256>>>(ei, W1, W2, E, N, eb);
    k_scan<<<nb, SCAN_B>>>(N, nb);
    k_reorder<<<eb, 256>>>(ei, x, E, N);
    k_gather<<<(MP * 32 + 255) / 256, 256>>>(N);

    dim3 grid(MP / 128, 4);
    k_gemm_mma<<<grid, 256, SM_HALFS * 2>>>(b1, b2, out, N);
}

// round 17
// speedup vs baseline: 1.8879x; 1.0139x over previous
#include <cuda_runtime.h>
#include <cuda_fp16.h>
#include <cstdint>

#define D 256
#define MAXN 50000
#define MP 50048            // M padded to multiple of 128
#define NB 512              // fused B rows (W1|W2 interleaved by n-tile)
#define MAXE 800000
#define SCAN_B 256

// ---------------- scratch (__device__ globals; allocation-free rule) --------
__device__ float  g_dinv[MAXN];
__device__ int    g_hist[MAXN];                 // zero at load; re-zeroed by k_reorder
__device__ int    g_off[MAXN + 1];
__device__ int    g_cursor[MAXN];
__device__ int    g_csr[MAXE];
__device__ unsigned long long g_state[256];     // lookback: (value<<2)|flag; zero at load
__device__ int    g_is64;
__device__ __half g_xs[MAXN * D];  // xs = dinv*x, fp16 gather source
__device__ __half g_A[MP * D];     // z (fp16), padded w/ zeros
__device__ __half g_B[NB * D];     // fused W (fp16) [n][k]

__device__ __forceinline__ long long load_idx(const void* ei, long long pos, int is64) {
    if (is64) return ((const long long*)ei)[pos];
    return (long long)((const int*)ei)[pos];
}

// ---------------- init: hist (self-detected dtype) + B prep ------------------
__global__ void k_init_hist(const void* __restrict__ ei,
                            const float* __restrict__ W1,
                            const float* __restrict__ W2,
                            int E, int n, int eb) {
    int b = blockIdx.x;
    if (b < eb) {
        __shared__ int sdet[4];
        const int* w = (const int*)ei;
        int acc = 0;
        if (threadIdx.x < 128) acc = w[threadIdx.x * 2 + 1];
#pragma unroll
        for (int o = 16; o > 0; o >>= 1) acc |= __shfl_xor_sync(0xffffffffu, acc, o);
        if (threadIdx.x < 128 && (threadIdx.x & 31) == 0) sdet[threadIdx.x >> 5] = acc;
        __syncthreads();
        int is64 = ((sdet[0] | sdet[1] | sdet[2] | sdet[3]) == 0) ? 1 : 0;
        int e = b * 256 + threadIdx.x;
        if (e < E) {
            long long dst = load_idx(ei, (long long)E + e, is64);
            if ((unsigned long long)dst < (unsigned long long)n)
                atomicAdd(&g_hist[dst], 1);
        }
        if (b == 0 && threadIdx.x == 0) g_is64 = is64;
    } else {
        int nrow = b - eb;           // 0..511
        int k = threadIdx.x;         // 0..255
        int j = nrow >> 7, l = nrow & 127;
        const float* W = (l < 64) ? W1 : W2;
        int col = j * 64 + (l & 63);
        g_B[nrow * D + k] = __float2half_rn(W[k * D + col]);
    }
}

// ---------------- single-pass scan (decoupled lookback) + dinv ---------------
__global__ void k_scan(int n, int nb) {
    __shared__ int s[SCAN_B];
    __shared__ int sprefix;
    int bid = blockIdx.x;
    int i = bid * SCAN_B + threadIdx.x;
    int v = (i < n) ? g_hist[i] : 0;
    s[threadIdx.x] = v;
    __syncthreads();
#pragma unroll
    for (int o = 1; o < SCAN_B; o <<= 1) {
        int t = (threadIdx.x >= o) ? s[threadIdx.x - o] : 0;
        __syncthreads();
        s[threadIdx.x] += t;
        __syncthreads();
    }
    int incl = s[threadIdx.x];
    int total = s[SCAN_B - 1];

    if (threadIdx.x == 0) {
        if (bid == 0) {
            atomicExch(&g_state[0], ((unsigned long long)total << 2) | 2ull);
            sprefix = 0;
        } else {
            atomicExch(&g_state[bid], ((unsigned long long)total << 2) | 1ull);
            int run = 0;
            int p = bid - 1;
            while (p >= 0) {
                unsigned long long st;
                do { st = atomicAdd(&g_state[p], 0ull); } while ((st & 3ull) == 0ull);
                run += (int)(st >> 2);
                if ((st & 3ull) == 2ull) break;
                p--;
            }
            atomicExch(&g_state[bid],
                       ((unsigned long long)(run + total) << 2) | 2ull);
            sprefix = run;
        }
    }
    __syncthreads();
    int spine = sprefix;
    if (i < n) {
        int o = spine + incl - v;
        g_off[i] = o;
        g_cursor[i] = o;
        g_dinv[i] = rsqrtf((float)g_hist[i] + 1.0f);   // +1 self loop
    }
    if (bid == nb - 1 && threadIdx.x == 0) g_off[n] = spine + total;
}

// ---------------- reorder + xs conversion + deferred re-zero -----------------
__global__ void k_reorder(const void* __restrict__ ei, const float* __restrict__ x,
                          int E, int n) {
    int t = blockIdx.x * blockDim.x + threadIdx.x;
    if (t < E) {
        int is64 = g_is64;
        long long s = load_idx(ei, t, is64);
        long long d = load_idx(ei, (long long)E + t, is64);
        if ((unsigned long long)d < (unsigned long long)n) {
            int pos = atomicAdd(&g_cursor[d], 1);
            int sv = ((unsigned long long)s < (unsigned long long)n) ? (int)s : (int)d;
            g_csr[pos] = sv;
        }
    }
    if (t < n) g_hist[t] = 0;
    if (t < 256) g_state[t] = 0ull;
    const float4* x4 = reinterpret_cast<const float4*>(x);
    int total = n * 32;
    int stride = gridDim.x * blockDim.x;
    for (int u = t; u < total; u += stride) {
        int row = u >> 5;
        int lane = u & 31;
        float dv = __ldg(&g_dinv[row]);
        float4 v0 = x4[(size_t)row * 64 + lane * 2];
        float4 v1 = x4[(size_t)row * 64 + lane * 2 + 1];
        union { __half h[8]; uint4 u4; } p;
        p.h[0] = __float2half_rn(v0.x * dv); p.h[1] = __float2half_rn(v0.y * dv);
        p.h[2] = __float2half_rn(v0.z * dv); p.h[3] = __float2half_rn(v0.w * dv);
        p.h[4] = __float2half_rn(v1.x * dv); p.h[5] = __float2half_rn(v1.y * dv);
        p.h[6] = __float2half_rn(v1.z * dv); p.h[7] = __float2half_rn(v1.w * dv);
        reinterpret_cast<uint4*>(g_xs)[u] = p.u4;
    }
}

// ---------------- fused gather + norm -> fp16 z ------------------------------
// One warp per node row r, lane covers 8 cols (one uint4 of fp16).
// Edges in GROUPS OF 4: two-level fp16 __hadd2 tree, one fp32 convert+add
// per group; then pair; then single tail.
//   z = dinv[r] * (xs[r] + sum_e xs[csr[e]])
__global__ __launch_bounds__(256)
void k_gather(int M) {
    int warp = (blockIdx.x * blockDim.x + threadIdx.x) >> 5;
    int lane = threadIdx.x & 31;
    if (warp >= MP) return;
    int r = warp;

    union { __half h[8]; uint4 u; } ph;

    if (r < M) {
        const uint4* xs4 = reinterpret_cast<const uint4*>(g_xs);
        float a[8];
        {
            union { uint4 u; __half2 h2[4]; } v;
            v.u = xs4[(size_t)r * 32 + lane];
#pragma unroll
            for (int q = 0; q < 4; q++) {
                float2 f = __half22float2(v.h2[q]);
                a[q * 2] = f.x; a[q * 2 + 1] = f.y;
            }
        }
        int beg = g_off[r];
        int end = g_off[r + 1];
        for (int base = beg; base < end; base += 32) {
            int cnt = min(32, end - base);
            int idx = (lane < cnt) ? g_csr[base + lane] : 0;
            int i = 0;
            for (; i + 4 <= cnt; i += 4) {
                int s0 = __shfl_sync(0xffffffffu, idx, i);
                int s1 = __shfl_sync(0xffffffffu, idx, i + 1);
                int s2 = __shfl_sync(0xffffffffu, idx, i + 2);
                int s3 = __shfl_sync(0xffffffffu, idx, i + 3);
                union { uint4 u; __half2 h2[4]; } v0, v1, v2, v3;
                v0.u = xs4[(size_t)s0 * 32 + lane];
                v1.u = xs4[(size_t)s1 * 32 + lane];
                v2.u = xs4[(size_t)s2 * 32 + lane];
                v3.u = xs4[(size_t)s3 * 32 + lane];
#pragma unroll
                for (int q = 0; q < 4; q++) {
                    __half2 h01 = __hadd2(v0.h2[q], v1.h2[q]);
                    __half2 h23 = __hadd2(v2.h2[q], v3.h2[q]);
                    __half2 hs  = __hadd2(h01, h23);
                    float2 f = __half22float2(hs);
                    a[q * 2]     += f.x;
                    a[q * 2 + 1] += f.y;
                }
            }
            if (i + 2 <= cnt) {
                int s0 = __shfl_sync(0xffffffffu, idx, i);
                int s1 = __shfl_sync(0xffffffffu, idx, i + 1);
                union { uint4 u; __half2 h2[4]; } v0, v1;
                v0.u = xs4[(size_t)s0 * 32 + lane];
                v1.u = xs4[(size_t)s1 * 32 + lane];
#pragma unroll
                for (int q = 0; q < 4; q++) {
                    __half2 hs = __hadd2(v0.h2[q], v1.h2[q]);
                    float2 f = __half22float2(hs);
                    a[q * 2]     += f.x;
                    a[q * 2 + 1] += f.y;
                }
                i += 2;
            }
            if (i < cnt) {
                int s0 = __shfl_sync(0xffffffffu, idx, i);
                union { uint4 u; __half2 h2[4]; } v0;
                v0.u = xs4[(size_t)s0 * 32 + lane];
#pragma unroll
                for (int q = 0; q < 4; q++) {
                    float2 f = __half22float2(v0.h2[q]);
                    a[q * 2]     += f.x;
                    a[q * 2 + 1] += f.y;
                }
            }
        }
        float dv = g_dinv[r];
#pragma unroll
        for (int e = 0; e < 8; e++)
            ph.h[e] = __float2half_rn(a[e] * dv);
    } else {
        ph.u = make_uint4(0, 0, 0, 0);
    }
    reinterpret_cast<uint4*>(g_A)[(size_t)r * 32 + lane] = ph.u;
}

// ---------------- mma / async helpers ---------------------------------------
__device__ __forceinline__ void mma16816(float c[4], const uint32_t a[4],
                                         const uint32_t b[2]) {
    asm volatile(
        "mma.sync.aligned.m16n8k16.row.col.f32.f16.f16.f32 "
        "{%0,%1,%2,%3}, {%4,%5,%6,%7}, {%8,%9}, {%0,%1,%2,%3};"
        : "+f"(c[0]), "+f"(c[1]), "+f"(c[2]), "+f"(c[3])
        : "r"(a[0]), "r"(a[1]), "r"(a[2]), "r"(a[3]), "r"(b[0]), "r"(b[1]));
}
__device__ __forceinline__ void cp16(uint32_t saddr, const void* g) {
    asm volatile("cp.async.cg.shared.global [%0], [%1], 16;"
                 :: "r"(saddr), "l"(g) : "memory");
}
__device__ __forceinline__ void cp_commit() {
    asm volatile("cp.async.commit_group;" ::: "memory");
}
__device__ __forceinline__ void ldsm_x4(uint32_t& r0, uint32_t& r1,
                                        uint32_t& r2, uint32_t& r3, uint32_t a) {
    asm volatile("ldmatrix.sync.aligned.m8n8.x4.shared.b16 {%0,%1,%2,%3}, [%4];"
                 : "=r"(r0), "=r"(r1), "=r"(r2), "=r"(r3) : "r"(a));
}
__device__ __forceinline__ uint32_t smem_u32(const void* p) {
    uint32_t a;
    asm("{ .reg .u64 t; cvta.to.shared.u64 t, %1; cvt.u32.u64 %0, t; }"
        : "=r"(a) : "l"(p));
    return a;
}

// ---------------- HMMA fp16 dual GEMM, cp.async 2-stage (R12 config) --------
#define PITCH 40
#define A_PLANE (128 * PITCH)                 // 5120 halfs
#define B_STAGE (128 * PITCH)                 // 5120 halfs (64 W1 + 64 W2 rows)
#define B_BASE  (2 * A_PLANE)
#define SM_HALFS (B_BASE + 2 * B_STAGE)       // 20480 halfs = 40 KB

__global__ __launch_bounds__(256, 2)
void k_gemm_mma(const float* __restrict__ b1, const float* __restrict__ b2,
                float* __restrict__ out, int M) {
    extern __shared__ uint16_t sm[];
    uint32_t sb = smem_u32(sm);

    int tid = threadIdx.x;
    int wid = tid >> 5;
    int lane = tid & 31;
    int wm = wid >> 1;
    int wn = wid & 1;
    int g = lane >> 2;
    int tig = lane & 3;
    int rowBase = blockIdx.x * 128;
    int j = blockIdx.y;
    int cb = j * 64;

    float acc1[2][4][4] = {};
    float acc2[2][4][4] = {};

    const uint4* A4 = reinterpret_cast<const uint4*>(g_A);
    const uint4* B4 = reinterpret_cast<const uint4*>(g_B);

    int lr = tid >> 2;           // 0..63
    int lkg = tid & 3;           // 16B chunk

    auto issue = [&](int kc, int st) {
        int kb4 = kc * 4;
#pragma unroll
        for (int it = 0; it < 2; it++) {
            int r = lr + it * 64;
            uint32_t sa = sb + (st * A_PLANE + r * PITCH + lkg * 8) * 2;
            cp16(sa, &A4[(size_t)(rowBase + r) * 32 + kb4 + lkg]);
            uint32_t bo = sb + (B_BASE + st * B_STAGE + r * PITCH + lkg * 8) * 2;
            cp16(bo, &B4[(size_t)(j * 128 + r) * 32 + kb4 + lkg]);
        }
        cp_commit();
    };

    issue(0, 0);

    int aRowSel = lane & 15;
    int aColSel = (lane >> 4) << 3;
    int bm = lane >> 3;
    int bRowSel = ((bm >> 1) << 3) + (lane & 7);
    int bColSel = (bm & 1) << 3;

    for (int kc = 0; kc < 8; kc++) {
        int st = kc & 1;
        if (kc < 7) issue(kc + 1, st ^ 1);
        if (kc < 7) asm volatile("cp.async.wait_group 1;" ::: "memory");
        else        asm volatile("cp.async.wait_group 0;" ::: "memory");
        __syncthreads();

        uint32_t aS = sb + (st * A_PLANE) * 2;
        uint32_t bS = sb + (B_BASE + st * B_STAGE) * 2;

#pragma unroll
        for (int ks = 0; ks < 2; ks++) {
            int kb = ks * 16;
            uint32_t ah[2][4];
#pragma unroll
            for (int mb = 0; mb < 2; mb++) {
                int row = wm * 32 + mb * 16 + aRowSel;
                uint32_t off = (row * PITCH + kb + aColSel) * 2;
                ldsm_x4(ah[mb][0], ah[mb][1], ah[mb][2], ah[mb][3], aS + off);
            }
            uint32_t bf1[4][2], bf2[4][2];
#pragma unroll
            for (int q = 0; q < 2; q++) {
                int n = wn * 32 + q * 16 + bRowSel;
                uint32_t a1 = bS + (n * PITCH + kb + bColSel) * 2;
                uint32_t a2 = bS + ((n + 64) * PITCH + kb + bColSel) * 2;
                ldsm_x4(bf1[q * 2][0], bf1[q * 2][1],
                        bf1[q * 2 + 1][0], bf1[q * 2 + 1][1], a1);
                ldsm_x4(bf2[q * 2][0], bf2[q * 2][1],
                        bf2[q * 2 + 1][0], bf2[q * 2 + 1][1], a2);
            }
#pragma unroll
            for (int mb = 0; mb < 2; mb++)
#pragma unroll
                for (int nb = 0; nb < 4; nb++) {
                    mma16816(acc1[mb][nb], ah[mb], bf1[nb]);
                    mma16816(acc2[mb][nb], ah[mb], bf2[nb]);
                }
        }
        __syncthreads();
    }

    // ---- epilogue: out = relu(acc1 + b1) + acc2 + b2 ----
#pragma unroll
    for (int mb = 0; mb < 2; mb++) {
#pragma unroll
        for (int nb = 0; nb < 4; nb++) {
            int c = cb + wn * 32 + nb * 8 + tig * 2;
            float bb1a = __ldg(&b1[c]), bb1b = __ldg(&b1[c + 1]);
            float bb2a = __ldg(&b2[c]), bb2b = __ldg(&b2[c + 1]);
#pragma unroll
            for (int h = 0; h < 2; h++) {
                int r = rowBase + wm * 32 + mb * 16 + g + h * 8;
                if (r >= M) continue;
                float z1 = acc1[mb][nb][h * 2]     + bb1a;
                float z2 = acc1[mb][nb][h * 2 + 1] + bb1b;
                z1 = z1 > 0.0f ? z1 : 0.0f;
                z2 = z2 > 0.0f ? z2 : 0.0f;
                float2 o;
                o.x = z1 + acc2[mb][nb][h * 2]     + bb2a;
                o.y = z2 + acc2[mb][nb][h * 2 + 1] + bb2b;
                *reinterpret_cast<float2*>(out + (size_t)r * D + c) = o;
            }
        }
    }
}

// ---------------- launch ----------------
extern "C" void kernel_launch(void* const* d_in, const int* in_sizes, int n_in,
                              void* d_out, int out_size) {
    const float* x  = (const float*)d_in[0];
    const void*  ei = d_in[1];
    const float* W1 = (const float*)d_in[2];
    const float* b1 = (const float*)d_in[3];
    const float* W2 = (const float*)d_in[4];
    const float* b2 = (const float*)d_in[5];
    float* out      = (float*)d_out;

    int N = in_sizes[0] / D;   // 50000
    int E = in_sizes[1] / 2;   // 800000
    int nb = (N + SCAN_B - 1) / SCAN_B;   // 196
    int eb = (E + 255) / 256;             // 3125

    static int smem_set = 0;
    if (!smem_set) {
        cudaFuncSetAttribute(k_gemm_mma, cudaFuncAttributeMaxDynamicSharedMemorySize,
                             SM_HALFS * 2);
        smem_set = 1;
    }

    k_init_hist<<<eb + NB, 256>>>(ei, W1, W2, E, N, eb);
    k_scan<<<nb, SCAN_B>>>(N, nb);
    k_reorder<<<eb, 256>>>(ei, x, E, N);
    k_gather<<<(MP * 32 + 255) / 256, 256>>>(N);

    dim3 grid(MP / 128, 4);
    k_gemm_mma<<<grid, 256, SM_HALFS * 2>>>(b1, b2, out, N);
}